// round 2
// baseline (speedup 1.0000x reference)
#include <cuda_runtime.h>
#include <cuda_fp16.h>
#include <cstdint>

#define N_HEADS 4
#define H_DIM   128
#define TOK_F   512
#define K_DIM   4096
#define BLK     32
#define STRIDE  16
#define MAXSEQ  256

#define NSTEPS  128          // K steps of 32
#define KT      32
#define B_BYTES 8192         // 128 n-rows x 32 k-halves (64B rows)

// ---------------- device scratch ----------------
__device__ int    g_bases[65536];
__device__ int    g_total_out;
__device__ __half g_wT[2][(size_t)K_DIM * H_DIM];   // [mat][n*4096 + k] = w[k*128+n]

static __device__ __forceinline__ uint32_t smem_u32(const void* p) {
    uint32_t a;
    asm("{ .reg .u64 t; cvta.to.shared.u64 t, %1; cvt.u32.u64 %0, t; }" : "=r"(a) : "l"(p));
    return a;
}

#define CP_ASYNC16(dst, src) \
    asm volatile("cp.async.cg.shared.global [%0], [%1], 16;" :: "r"(dst), "l"(src) : "memory")
#define CP_COMMIT() asm volatile("cp.async.commit_group;" ::: "memory")
#define CP_WAIT1()  asm volatile("cp.async.wait_group 1;" ::: "memory")

#define LDMATRIX_X4(r0, r1, r2, r3, addr) \
    asm volatile("ldmatrix.sync.aligned.m8n8.x4.shared.b16 {%0,%1,%2,%3}, [%4];" \
                 : "=r"(r0), "=r"(r1), "=r"(r2), "=r"(r3) : "r"(addr))

#define MMA16816(c, a0, a1, a2, a3, b0, b1) \
    asm volatile("mma.sync.aligned.m16n8k16.row.col.f32.f16.f16.f32 " \
                 "{%0,%1,%2,%3}, {%4,%5,%6,%7}, {%8,%9}, {%0,%1,%2,%3};" \
                 : "+f"((c)[0]), "+f"((c)[1]), "+f"((c)[2]), "+f"((c)[3]) \
                 : "r"(a0), "r"(a1), "r"(a2), "r"(a3), "r"(b0), "r"(b1))

// ---------------- kernel 1: ragged metadata ----------------
__global__ void setup_kernel(const int* __restrict__ cu, int nseq, float* __restrict__ dout) {
    __shared__ int s_cu[MAXSEQ + 1];
    if (threadIdx.x == 0) {
        int acc = 0;
        s_cu[0] = 0;
        for (int b = 0; b < nseq; b++) {
            int n = cu[b + 1] - cu[b];
            int ol = (n >= BLK) ? (n - BLK) / STRIDE : 0;
            acc += ol;
            s_cu[b + 1] = acc;
        }
        g_total_out = acc;
    }
    __syncthreads();
    int total = s_cu[nseq];
    for (int i = threadIdx.x; i <= nseq; i += blockDim.x)
        dout[(size_t)2 * total * 512 + i] = (float)s_cu[i];
    for (int o = threadIdx.x; o < total; o += blockDim.x) {
        int b = 0;
        while (s_cu[b + 1] <= o) b++;
        g_bases[o] = cu[b] + (o - s_cu[b]) * STRIDE;
    }
}

// ---------------- kernel 2: W transpose + fp16 convert ----------------
__global__ void wconv_kernel(const float* __restrict__ wk, const float* __restrict__ wv) {
    __shared__ float tile[32][33];
    const float* w = blockIdx.z ? wv : wk;
    __half* out = g_wT[blockIdx.z];
    int k0 = blockIdx.x * 32, n0 = blockIdx.y * 32;
    int tx = threadIdx.x, ty = threadIdx.y;   // (32, 8)
#pragma unroll
    for (int i = 0; i < 32; i += 8)
        tile[ty + i][tx] = w[(size_t)(k0 + ty + i) * H_DIM + n0 + tx];
    __syncthreads();
#pragma unroll
    for (int i = 0; i < 32; i += 8)
        out[(size_t)(n0 + ty + i) * K_DIM + k0 + tx] = __float2half_rn(tile[tx][ty + i]);
}

// ---------------- kernel 3: HMMA GEMM ----------------
// CTA: 256 thr, 8 warps in 4(M) x 2(N) grid; warp tile 32x64.
// M_CTA = 128 rows (32 output blocks), N = 128, K-step 32.
__global__ __launch_bounds__(256, 2)
void gemm_kernel(const float* __restrict__ kin, const float* __restrict__ vin,
                 float* __restrict__ dout) {
    __shared__ __align__(128) char sB[2][B_BYTES];

    const int tid = threadIdx.x;
    const int wid = tid >> 5;
    const int lid = tid & 31;
    const int total_out = g_total_out;
    const int o0 = blockIdx.x * 32;
    if (o0 >= total_out) return;

    const int mat = blockIdx.y;
    const float* __restrict__ x = mat ? vin : kin;
    const __half* __restrict__ wT = g_wT[mat];
    float* __restrict__ outp = dout + (size_t)mat * (size_t)total_out * 512;

    const int wr = wid >> 1;       // 0..3 : M position
    const int wc = wid & 1;        // 0..1 : N position
    const int l4 = lid >> 2;       // 0..7
    const int lc = lid & 3;        // 0..3

    // ---- A row pointers (fragment layout, direct gmem) ----
    // i = ma*2 + rh : row = wr*32 + ma*16 + rh*8 + l4
    const float* aptr[4];
#pragma unroll
    for (int i = 0; i < 4; i++) {
        int r = wr * 32 + (i >> 1) * 16 + (i & 1) * 8 + l4;
        int o = o0 + (r >> 2);
        if (o >= total_out) o = total_out - 1;
        aptr[i] = x + (size_t)g_bases[o] * TOK_F + (size_t)(r & 3) * H_DIM + lc * 2;
    }

    // ---- B cp.async src/dst (2 x 16B per thread per step) ----
    const __half* bsrc[2];
    uint32_t bdst[2];
    const uint32_t sbase = smem_u32(sB);
#pragma unroll
    for (int it = 0; it < 2; it++) {
        int chunk = it * 256 + tid;        // 0..511
        int n = chunk >> 2, c = chunk & 3;
        bsrc[it] = wT + (size_t)n * K_DIM + c * 8;
        bdst[it] = sbase + (uint32_t)(n * 64 + ((c ^ ((n >> 1) & 3)) * 16));
    }

    // ---- ldmatrix addresses: 4 pair-calls x 2 k16 sub-steps ----
    // call p covers n-atoms (2p, 2p+1). lane: t = lid>>3, tile = (ng = 2p + (t>>1), kc = t&1)
    uint32_t lmaddr[4][2];
    {
        int t = lid >> 3;
        int kc = t & 1;
#pragma unroll
        for (int p = 0; p < 4; p++) {
            int n = wc * 64 + (2 * p + (t >> 1)) * 8 + (lid & 7);
            int sw = (n >> 1) & 3;
#pragma unroll
            for (int k16i = 0; k16i < 2; k16i++) {
                int c = (k16i * 2 + kc) ^ sw;
                lmaddr[p][k16i] = sbase + (uint32_t)(n * 64 + c * 16);
            }
        }
    }

    float acc[2][8][4];
#pragma unroll
    for (int ma = 0; ma < 2; ma++)
#pragma unroll
        for (int na = 0; na < 8; na++)
#pragma unroll
            for (int q = 0; q < 4; q++) acc[ma][na][q] = 0.f;

    // ---- prologue: stage step 0 of B ----
#pragma unroll
    for (int it = 0; it < 2; it++) CP_ASYNC16(bdst[it], bsrc[it]);
    CP_COMMIT();

#pragma unroll 1
    for (int s = 0; s < NSTEPS; s++) {
        const int buf = s & 1;
        if (s + 1 < NSTEPS) {
            const int koff = (s + 1) * KT;
#pragma unroll
            for (int it = 0; it < 2; it++)
                CP_ASYNC16(bdst[it] + (buf ^ 1) * B_BYTES, bsrc[it] + koff);
        }
        CP_COMMIT();
        CP_WAIT1();
        __syncthreads();

        // ---- A loads: 2 m-atoms x 2 k16 x (4 float2) ----
        const int aoff = (s >> 2) * TOK_F + (s & 3) * KT;   // j*512 + d0
        uint32_t afr[2][2][4];                               // [ma][k16][a0..a3]
#pragma unroll
        for (int ma = 0; ma < 2; ma++)
#pragma unroll
            for (int k16i = 0; k16i < 2; k16i++) {
                const int col = aoff + k16i * 16;
                float2 v0 = *(const float2*)(aptr[ma * 2 + 0] + col);
                float2 v1 = *(const float2*)(aptr[ma * 2 + 1] + col);
                float2 v2 = *(const float2*)(aptr[ma * 2 + 0] + col + 8);
                float2 v3 = *(const float2*)(aptr[ma * 2 + 1] + col + 8);
                __half2 h0 = __floats2half2_rn(v0.x, v0.y);
                __half2 h1 = __floats2half2_rn(v1.x, v1.y);
                __half2 h2 = __floats2half2_rn(v2.x, v2.y);
                __half2 h3 = __floats2half2_rn(v3.x, v3.y);
                afr[ma][k16i][0] = *reinterpret_cast<uint32_t*>(&h0);
                afr[ma][k16i][1] = *reinterpret_cast<uint32_t*>(&h1);
                afr[ma][k16i][2] = *reinterpret_cast<uint32_t*>(&h2);
                afr[ma][k16i][3] = *reinterpret_cast<uint32_t*>(&h3);
            }

        // ---- compute ----
#pragma unroll
        for (int k16i = 0; k16i < 2; k16i++) {
#pragma unroll
            for (int p = 0; p < 4; p++) {
                uint32_t q0, q1, q2, q3;
                LDMATRIX_X4(q0, q1, q2, q3, lmaddr[p][k16i] + buf * B_BYTES);
#pragma unroll
                for (int ma = 0; ma < 2; ma++) {
                    MMA16816(acc[ma][2 * p + 0], afr[ma][k16i][0], afr[ma][k16i][1],
                             afr[ma][k16i][2], afr[ma][k16i][3], q0, q1);
                    MMA16816(acc[ma][2 * p + 1], afr[ma][k16i][0], afr[ma][k16i][1],
                             afr[ma][k16i][2], afr[ma][k16i][3], q2, q3);
                }
            }
        }
        __syncthreads();
    }

    // ---- epilogue: direct fp32 stores ----
    const int Rmax = total_out * 4;
#pragma unroll
    for (int ma = 0; ma < 2; ma++) {
#pragma unroll
        for (int na = 0; na < 8; na++) {
            int col = wc * 64 + na * 8 + lc * 2;
            int R0 = o0 * 4 + wr * 32 + ma * 16 + l4;
            if (R0 < Rmax) {
                float2 st = make_float2(acc[ma][na][0], acc[ma][na][1]);
                *(float2*)(outp + (size_t)R0 * 128 + col) = st;
            }
            int R1 = R0 + 8;
            if (R1 < Rmax) {
                float2 st = make_float2(acc[ma][na][2], acc[ma][na][3]);
                *(float2*)(outp + (size_t)R1 * 128 + col) = st;
            }
        }
    }
}

// ---------------- launch ----------------
extern "C" void kernel_launch(void* const* d_in, const int* in_sizes, int n_in,
                              void* d_out, int out_size) {
    const float* k  = (const float*)d_in[0];
    const float* v  = (const float*)d_in[1];
    const float* wk = (const float*)d_in[2];
    const float* wv = (const float*)d_in[3];
    const int*   cu = (const int*)d_in[4];
    int nseq = in_sizes[4] - 1;
    int total_tokens = in_sizes[0] / (N_HEADS * H_DIM);

    setup_kernel<<<1, 256>>>(cu, nseq, (float*)d_out);
    wconv_kernel<<<dim3(K_DIM / 32, H_DIM / 32, 2), dim3(32, 8)>>>(wk, wv);

    int max_out = total_tokens / STRIDE;
    int ntiles = (max_out + 31) / 32;
    gemm_kernel<<<dim3(ntiles, 2), 256>>>(k, v, (float*)d_out);
}

// round 4
// speedup vs baseline: 1.2883x; 1.2883x over previous
#include <cuda_runtime.h>
#include <cuda_fp16.h>
#include <cstdint>

#define N_HEADS 4
#define H_DIM   128
#define TOK_F   512
#define K_DIM   4096
#define BLK     32
#define STRIDE  16
#define MAXSEQ  256

#define NSTEPS  64
#define KT      64            // K halves per step
#define TILE_BYTES 16384      // 128 rows x 128B
#define SMEM_GEMM (5 * TILE_BYTES + 256)   // A x2, B x3, ctrl

// ---------------- device scratch ----------------
__device__ int    g_bases[65536];
__device__ int    g_total_out;
__device__ __half g_wT[2][(size_t)K_DIM * H_DIM];   // [mat][n*4096 + k] = w[k*128+n]

static __device__ __forceinline__ uint32_t smem_u32(const void* p) {
    uint32_t a;
    asm("{ .reg .u64 t; cvta.to.shared.u64 t, %1; cvt.u32.u64 %0, t; }" : "=r"(a) : "l"(p));
    return a;
}

#define CP_ASYNC16(dst, src) \
    asm volatile("cp.async.cg.shared.global [%0], [%1], 16;" :: "r"(dst), "l"(src) : "memory")
#define CP_COMMIT() asm volatile("cp.async.commit_group;" ::: "memory")
#define CP_WAIT1()  asm volatile("cp.async.wait_group 1;" ::: "memory")

#define LDMATRIX_X4(r0, r1, r2, r3, addr) \
    asm volatile("ldmatrix.sync.aligned.m8n8.x4.shared.b16 {%0,%1,%2,%3}, [%4];" \
                 : "=r"(r0), "=r"(r1), "=r"(r2), "=r"(r3) : "r"(addr))

#define MMA16816(c, a0, a1, a2, a3, b0, b1) \
    asm volatile("mma.sync.aligned.m16n8k16.row.col.f32.f16.f16.f32 " \
                 "{%0,%1,%2,%3}, {%4,%5,%6,%7}, {%8,%9}, {%0,%1,%2,%3};" \
                 : "+f"((c)[0]), "+f"((c)[1]), "+f"((c)[2]), "+f"((c)[3]) \
                 : "r"(a0), "r"(a1), "r"(a2), "r"(a3), "r"(b0), "r"(b1))

// ---------------- kernel 1: ragged metadata ----------------
__global__ void setup_kernel(const int* __restrict__ cu, int nseq, float* __restrict__ dout) {
    __shared__ int s_ol[MAXSEQ];
    __shared__ int s_cu[MAXSEQ + 1];
    int t = threadIdx.x;
    if (t < nseq) {
        int n = cu[t + 1] - cu[t];
        s_ol[t] = (n >= BLK) ? (n - BLK) / STRIDE : 0;
    }
    __syncthreads();
    if (t == 0) {
        int acc = 0;
        s_cu[0] = 0;
        for (int b = 0; b < nseq; b++) { acc += s_ol[b]; s_cu[b + 1] = acc; }
        g_total_out = acc;
    }
    __syncthreads();
    int total = s_cu[nseq];
    for (int i = t; i <= nseq; i += blockDim.x)
        dout[(size_t)2 * total * 512 + i] = (float)s_cu[i];
    for (int o = t; o < total; o += blockDim.x) {
        int b = 0;
        while (s_cu[b + 1] <= o) b++;
        g_bases[o] = cu[b] + (o - s_cu[b]) * STRIDE;
    }
}

// ---------------- kernel 2: W transpose + fp16 convert ----------------
__global__ void wconv_kernel(const float* __restrict__ wk, const float* __restrict__ wv) {
    __shared__ float tile[32][33];
    const float* w = blockIdx.z ? wv : wk;
    __half* out = g_wT[blockIdx.z];
    int k0 = blockIdx.x * 32, n0 = blockIdx.y * 32;
    int tx = threadIdx.x, ty = threadIdx.y;   // (32, 8)
#pragma unroll
    for (int i = 0; i < 32; i += 8)
        tile[ty + i][tx] = w[(size_t)(k0 + ty + i) * H_DIM + n0 + tx];
    __syncthreads();
#pragma unroll
    for (int i = 0; i < 32; i += 8)
        out[(size_t)(n0 + ty + i) * K_DIM + k0 + tx] = __float2half_rn(tile[tx][ty + i]);
}

// ---------------- kernel 3: HMMA GEMM ----------------
// 512 thr = 16 warps in 4(M) x 4(N); warp tile 32x32; CTA tile 128x128; K-step 64.
// A: LDG.128 + cvt + swizzled STS, double-buffered (STS after compute -> safe).
// B: cp.async, TRIPLE-buffered; copy for s+2 issued after syncthreads(s) -> race-free.
__global__ __launch_bounds__(512, 1)
void gemm_kernel(const float* __restrict__ kin, const float* __restrict__ vin,
                 float* __restrict__ dout) {
    extern __shared__ __align__(128) char smem[];
    const uint32_t sa = smem_u32(smem);           // A: 2 x 16KB
    const uint32_t sb = sa + 2 * TILE_BYTES;      // B: 3 x 16KB
    int* s_base = (int*)(smem + 5 * TILE_BYTES);

    const int tid = threadIdx.x;
    const int wid = tid >> 5;
    const int lid = tid & 31;
    const int total_out = g_total_out;
    const int o0 = blockIdx.x * 32;
    if (o0 >= total_out) return;

    const int mat = blockIdx.y;
    const float* __restrict__ x = mat ? vin : kin;
    const __half* __restrict__ wT = g_wT[mat];
    float* __restrict__ outp = dout + (size_t)mat * (size_t)total_out * 512;

    if (tid < 32) {
        int o = o0 + tid;
        if (o >= total_out) o = total_out - 1;
        s_base[tid] = g_bases[o];
    }
    __syncthreads();

    // ---- A global pointer: thread handles row m = tid>>2, float cols q*16..+15 ----
    const int m_row = tid >> 2;
    const int q     = tid & 3;
    const float* aptr = x + (size_t)s_base[m_row >> 2] * TOK_F
                          + (size_t)(m_row & 3) * H_DIM + q * 16;
    const uint32_t ast0 = (uint32_t)(m_row * 128 + (((2 * q)     ^ (m_row & 7)) * 16));
    const uint32_t ast1 = (uint32_t)(m_row * 128 + (((2 * q + 1) ^ (m_row & 7)) * 16));

    // ---- B cp.async: thread handles n = tid>>2, chunks (tid&3)*2 + {0,1} ----
    const __half* bsrc[2];
    uint32_t bdst[2];
#pragma unroll
    for (int i = 0; i < 2; i++) {
        int n = tid >> 2, c = (tid & 3) * 2 + i;
        bsrc[i] = wT + (size_t)n * K_DIM + c * 8;
        bdst[i] = sb + (uint32_t)(n * 128 + ((c ^ (n & 7)) * 16));
    }

    // ---- ldmatrix addresses (offsets within one tile) ----
    const int wr = wid >> 2;       // M position 0..3
    const int wc = wid & 3;        // N position 0..3
    const int g  = lid >> 3;       // tile group 0..3
    const int l7 = lid & 7;
    uint32_t lma[2][4];
#pragma unroll
    for (int ma = 0; ma < 2; ma++) {
        int r = wr * 32 + ma * 16 + (g & 1) * 8 + l7;
#pragma unroll
        for (int k16i = 0; k16i < 4; k16i++) {
            int c = (2 * k16i + (g >> 1)) ^ (r & 7);
            lma[ma][k16i] = sa + (uint32_t)(r * 128 + c * 16);
        }
    }
    uint32_t lmb[2][4];
#pragma unroll
    for (int p = 0; p < 2; p++) {
        int n = wc * 32 + (2 * p + (g >> 1)) * 8 + l7;
#pragma unroll
        for (int k16i = 0; k16i < 4; k16i++) {
            int c = (2 * k16i + (g & 1)) ^ (n & 7);
            lmb[p][k16i] = sb + (uint32_t)(n * 128 + c * 16);
        }
    }

    float acc[2][4][4];
#pragma unroll
    for (int ma = 0; ma < 2; ma++)
#pragma unroll
        for (int na = 0; na < 4; na++)
#pragma unroll
            for (int e = 0; e < 4; e++) acc[ma][na][e] = 0.f;

    // ---- prologue: B steps 0 and 1 (two cp.async groups), A step 0 (direct STS) ----
#pragma unroll
    for (int i = 0; i < 2; i++) CP_ASYNC16(bdst[i], bsrc[i]);
    CP_COMMIT();
#pragma unroll
    for (int i = 0; i < 2; i++) CP_ASYNC16(bdst[i] + TILE_BYTES, bsrc[i] + KT);
    CP_COMMIT();
    {
        float4 rv[4];
#pragma unroll
        for (int i = 0; i < 4; i++) rv[i] = *(const float4*)(aptr + 4 * i);
        __half2 h;
        uint4 s0, s1;
        h = __floats2half2_rn(rv[0].x, rv[0].y); s0.x = *(uint32_t*)&h;
        h = __floats2half2_rn(rv[0].z, rv[0].w); s0.y = *(uint32_t*)&h;
        h = __floats2half2_rn(rv[1].x, rv[1].y); s0.z = *(uint32_t*)&h;
        h = __floats2half2_rn(rv[1].z, rv[1].w); s0.w = *(uint32_t*)&h;
        h = __floats2half2_rn(rv[2].x, rv[2].y); s1.x = *(uint32_t*)&h;
        h = __floats2half2_rn(rv[2].z, rv[2].w); s1.y = *(uint32_t*)&h;
        h = __floats2half2_rn(rv[3].x, rv[3].y); s1.z = *(uint32_t*)&h;
        h = __floats2half2_rn(rv[3].z, rv[3].w); s1.w = *(uint32_t*)&h;
        *(uint4*)(smem + ast0) = s0;
        *(uint4*)(smem + ast1) = s1;
    }

    int b3 = 0;                    // s % 3
#pragma unroll 1
    for (int s = 0; s < NSTEPS; s++) {
        // wait for B group of step s (keep 1 outstanding: step s+1)
        CP_WAIT1();
        __syncthreads();

        // issue B for step s+2 into slot (s+2)%3 -- safe: everyone is past step s-1
        if (s + 2 < NSTEPS) {
            int b3n = b3 + 2; if (b3n >= 3) b3n -= 3;
            const int koff = (s + 2) * KT;
#pragma unroll
            for (int i = 0; i < 2; i++)
                CP_ASYNC16(bdst[i] + b3n * TILE_BYTES, bsrc[i] + koff);
        }
        CP_COMMIT();

        // prefetch A for step s+1 into registers
        float4 rv[4];
        const bool pf = (s + 1 < NSTEPS);
        if (pf) {
            const int aoff = ((s + 1) >> 1) * TOK_F + ((s + 1) & 1) * KT;
#pragma unroll
            for (int i = 0; i < 4; i++) rv[i] = *(const float4*)(aptr + aoff + 4 * i);
        }

        // compute from A slot (s&1), B slot (s%3)
        const uint32_t abuf = (uint32_t)((s & 1) * TILE_BYTES);
        const uint32_t bbuf = (uint32_t)(b3 * TILE_BYTES);
#pragma unroll
        for (int k16i = 0; k16i < 4; k16i++) {
            uint32_t a0[4], a1[4], b0[4], b1[4];
            LDMATRIX_X4(a0[0], a0[1], a0[2], a0[3], lma[0][k16i] + abuf);
            LDMATRIX_X4(a1[0], a1[1], a1[2], a1[3], lma[1][k16i] + abuf);
            LDMATRIX_X4(b0[0], b0[1], b0[2], b0[3], lmb[0][k16i] + bbuf);
            LDMATRIX_X4(b1[0], b1[1], b1[2], b1[3], lmb[1][k16i] + bbuf);
            MMA16816(acc[0][0], a0[0], a0[1], a0[2], a0[3], b0[0], b0[1]);
            MMA16816(acc[0][1], a0[0], a0[1], a0[2], a0[3], b0[2], b0[3]);
            MMA16816(acc[0][2], a0[0], a0[1], a0[2], a0[3], b1[0], b1[1]);
            MMA16816(acc[0][3], a0[0], a0[1], a0[2], a0[3], b1[2], b1[3]);
            MMA16816(acc[1][0], a1[0], a1[1], a1[2], a1[3], b0[0], b0[1]);
            MMA16816(acc[1][1], a1[0], a1[1], a1[2], a1[3], b0[2], b0[3]);
            MMA16816(acc[1][2], a1[0], a1[1], a1[2], a1[3], b1[0], b1[1]);
            MMA16816(acc[1][3], a1[0], a1[1], a1[2], a1[3], b1[2], b1[3]);
        }

        // store prefetched A into slot (s+1)&1 -- safe: after syncthreads(s),
        // nobody is still reading that slot (its readers were step s-1).
        if (pf) {
            const uint32_t nbuf = (uint32_t)(((s + 1) & 1) * TILE_BYTES);
            __half2 h;
            uint4 s0, s1;
            h = __floats2half2_rn(rv[0].x, rv[0].y); s0.x = *(uint32_t*)&h;
            h = __floats2half2_rn(rv[0].z, rv[0].w); s0.y = *(uint32_t*)&h;
            h = __floats2half2_rn(rv[1].x, rv[1].y); s0.z = *(uint32_t*)&h;
            h = __floats2half2_rn(rv[1].z, rv[1].w); s0.w = *(uint32_t*)&h;
            h = __floats2half2_rn(rv[2].x, rv[2].y); s1.x = *(uint32_t*)&h;
            h = __floats2half2_rn(rv[2].z, rv[2].w); s1.y = *(uint32_t*)&h;
            h = __floats2half2_rn(rv[3].x, rv[3].y); s1.z = *(uint32_t*)&h;
            h = __floats2half2_rn(rv[3].z, rv[3].w); s1.w = *(uint32_t*)&h;
            *(uint4*)(smem + ast0 + nbuf) = s0;
            *(uint4*)(smem + ast1 + nbuf) = s1;
        }

        b3 += 1; if (b3 >= 3) b3 -= 3;
    }

    // ---- epilogue ----
    const int Rmax = total_out * 4;
    const int l4 = lid >> 2, lc = lid & 3;
#pragma unroll
    for (int ma = 0; ma < 2; ma++) {
        int R0 = o0 * 4 + wr * 32 + ma * 16 + l4;
#pragma unroll
        for (int na = 0; na < 4; na++) {
            int col = wc * 32 + na * 8 + lc * 2;
            if (R0 < Rmax)
                *(float2*)(outp + (size_t)R0 * 128 + col) =
                    make_float2(acc[ma][na][0], acc[ma][na][1]);
            if (R0 + 8 < Rmax)
                *(float2*)(outp + (size_t)(R0 + 8) * 128 + col) =
                    make_float2(acc[ma][na][2], acc[ma][na][3]);
        }
    }
}

// ---------------- launch ----------------
extern "C" void kernel_launch(void* const* d_in, const int* in_sizes, int n_in,
                              void* d_out, int out_size) {
    const float* k  = (const float*)d_in[0];
    const float* v  = (const float*)d_in[1];
    const float* wk = (const float*)d_in[2];
    const float* wv = (const float*)d_in[3];
    const int*   cu = (const int*)d_in[4];
    int nseq = in_sizes[4] - 1;
    int total_tokens = in_sizes[0] / (N_HEADS * H_DIM);

    setup_kernel<<<1, 256>>>(cu, nseq, (float*)d_out);
    wconv_kernel<<<dim3(K_DIM / 32, H_DIM / 32, 2), dim3(32, 8)>>>(wk, wv);

    int max_out = total_tokens / STRIDE;
    int ntiles = (max_out + 31) / 32;
    cudaFuncSetAttribute(gemm_kernel, cudaFuncAttributeMaxDynamicSharedMemorySize, SMEM_GEMM);
    gemm_kernel<<<dim3(ntiles, 2), 512, SMEM_GEMM>>>(k, v, (float*)d_out);
}

// round 5
// speedup vs baseline: 1.4152x; 1.0985x over previous
#include <cuda_runtime.h>
#include <cuda_fp16.h>
#include <cstdint>

#define N_HEADS 4
#define H_DIM   128
#define TOK_F   512
#define K_DIM   4096
#define BLK     32
#define STRIDE  16
#define MAXSEQ  256

#define NSTEPS  64
#define KT      64            // K halves per step
#define TILE_BYTES 16384      // 128 rows x 128B
#define SMEM_GEMM (5 * TILE_BYTES + 256)   // A x2, B x3, ctrl

// ---------------- device scratch ----------------
__device__ int    g_bases[65536];
__device__ int    g_total_out;
__device__ __half g_wT[2][(size_t)K_DIM * H_DIM];   // [mat][n*4096 + k] = w[k*128+n]

static __device__ __forceinline__ uint32_t smem_u32(const void* p) {
    uint32_t a;
    asm("{ .reg .u64 t; cvta.to.shared.u64 t, %1; cvt.u32.u64 %0, t; }" : "=r"(a) : "l"(p));
    return a;
}

#define CP_ASYNC16(dst, src) \
    asm volatile("cp.async.cg.shared.global [%0], [%1], 16;" :: "r"(dst), "l"(src) : "memory")
#define CP_COMMIT() asm volatile("cp.async.commit_group;" ::: "memory")
#define CP_WAIT1()  asm volatile("cp.async.wait_group 1;" ::: "memory")

#define LDMATRIX_X4(r0, r1, r2, r3, addr) \
    asm volatile("ldmatrix.sync.aligned.m8n8.x4.shared.b16 {%0,%1,%2,%3}, [%4];" \
                 : "=r"(r0), "=r"(r1), "=r"(r2), "=r"(r3) : "r"(addr))

// fp16-accumulate MMA: D,C packed half2 x2
#define MMAF16(c, a0, a1, a2, a3, b0, b1) \
    asm volatile("mma.sync.aligned.m16n8k16.row.col.f16.f16.f16.f16 " \
                 "{%0,%1}, {%2,%3,%4,%5}, {%6,%7}, {%0,%1};" \
                 : "+r"((c)[0]), "+r"((c)[1]) \
                 : "r"(a0), "r"(a1), "r"(a2), "r"(a3), "r"(b0), "r"(b1))

// ---------------- kernel 1: prep = ragged metadata + W transpose/convert ----------------
// blocks [0, 1024): wconv; block 1024: setup. blockDim (32, 8).
__global__ void prep_kernel(const int* __restrict__ cu, int nseq,
                            const float* __restrict__ wk, const float* __restrict__ wv,
                            float* __restrict__ dout) {
    if (blockIdx.x == 1024) {
        __shared__ int s_ol[MAXSEQ];
        __shared__ int s_cu[MAXSEQ + 1];
        int t = threadIdx.y * 32 + threadIdx.x;
        if (t < nseq) {
            int n = cu[t + 1] - cu[t];
            s_ol[t] = (n >= BLK) ? (n - BLK) / STRIDE : 0;
        }
        __syncthreads();
        if (t == 0) {
            int acc = 0;
            s_cu[0] = 0;
            for (int b = 0; b < nseq; b++) { acc += s_ol[b]; s_cu[b + 1] = acc; }
            g_total_out = acc;
        }
        __syncthreads();
        int total = s_cu[nseq];
        for (int i = t; i <= nseq; i += 256)
            dout[(size_t)2 * total * 512 + i] = (float)s_cu[i];
        for (int o = t; o < total; o += 256) {
            int b = 0;
            while (s_cu[b + 1] <= o) b++;
            g_bases[o] = cu[b] + (o - s_cu[b]) * STRIDE;
        }
        return;
    }
    __shared__ float tile[32][33];
    int bx = blockIdx.x;
    int z   = bx >> 9;            // 0..1
    int rem = bx & 511;
    int kb  = rem & 127;          // 0..127
    int nb  = rem >> 7;           // 0..3
    const float* w = z ? wv : wk;
    __half* out = g_wT[z];
    int k0 = kb * 32, n0 = nb * 32;
    int tx = threadIdx.x, ty = threadIdx.y;   // (32, 8)
#pragma unroll
    for (int i = 0; i < 32; i += 8)
        tile[ty + i][tx] = w[(size_t)(k0 + ty + i) * H_DIM + n0 + tx];
    __syncthreads();
#pragma unroll
    for (int i = 0; i < 32; i += 8)
        out[(size_t)(n0 + ty + i) * K_DIM + k0 + tx] = __float2half_rn(tile[tx][ty + i]);
}

// ---------------- kernel 2: HMMA GEMM (fp16 accumulate + fp32 flush) ----------------
// 512 thr = 16 warps in 4(M) x 4(N); warp tile 32x32; CTA tile 128x128; K-step 64.
// fp16 acc over a 2-step window (128 K-halves), flushed into fp32 regs.
__global__ __launch_bounds__(512, 1)
void gemm_kernel(const float* __restrict__ kin, const float* __restrict__ vin,
                 float* __restrict__ dout) {
    extern __shared__ __align__(128) char smem[];
    const uint32_t sa = smem_u32(smem);           // A: 2 x 16KB
    const uint32_t sb = sa + 2 * TILE_BYTES;      // B: 3 x 16KB
    int* s_base = (int*)(smem + 5 * TILE_BYTES);

    const int tid = threadIdx.x;
    const int wid = tid >> 5;
    const int lid = tid & 31;
    const int total_out = g_total_out;
    const int o0 = blockIdx.x * 32;
    if (o0 >= total_out) return;

    const int mat = blockIdx.y;
    const float* __restrict__ x = mat ? vin : kin;
    const __half* __restrict__ wT = g_wT[mat];
    float* __restrict__ outp = dout + (size_t)mat * (size_t)total_out * 512;

    if (tid < 32) {
        int o = o0 + tid;
        if (o >= total_out) o = total_out - 1;
        s_base[tid] = g_bases[o];
    }
    __syncthreads();

    // ---- A global pointer: thread handles row m = tid>>2, float cols q*16..+15 ----
    const int m_row = tid >> 2;
    const int q     = tid & 3;
    const float* aptr = x + (size_t)s_base[m_row >> 2] * TOK_F
                          + (size_t)(m_row & 3) * H_DIM + q * 16;
    const uint32_t ast0 = (uint32_t)(m_row * 128 + (((2 * q)     ^ (m_row & 7)) * 16));
    const uint32_t ast1 = (uint32_t)(m_row * 128 + (((2 * q + 1) ^ (m_row & 7)) * 16));

    // ---- B cp.async: thread handles n = tid>>2, chunks (tid&3)*2 + {0,1} ----
    const __half* bsrc[2];
    uint32_t bdst[2];
#pragma unroll
    for (int i = 0; i < 2; i++) {
        int n = tid >> 2, c = (tid & 3) * 2 + i;
        bsrc[i] = wT + (size_t)n * K_DIM + c * 8;
        bdst[i] = sb + (uint32_t)(n * 128 + ((c ^ (n & 7)) * 16));
    }

    // ---- ldmatrix addresses (offsets within one tile) ----
    const int wr = wid >> 2;       // M position 0..3
    const int wc = wid & 3;        // N position 0..3
    const int g  = lid >> 3;       // tile group 0..3
    const int l7 = lid & 7;
    uint32_t lma[2][4];
#pragma unroll
    for (int ma = 0; ma < 2; ma++) {
        int r = wr * 32 + ma * 16 + (g & 1) * 8 + l7;
#pragma unroll
        for (int k16i = 0; k16i < 4; k16i++) {
            int c = (2 * k16i + (g >> 1)) ^ (r & 7);
            lma[ma][k16i] = sa + (uint32_t)(r * 128 + c * 16);
        }
    }
    uint32_t lmb[2][4];
#pragma unroll
    for (int p = 0; p < 2; p++) {
        int n = wc * 32 + (2 * p + (g >> 1)) * 8 + l7;
#pragma unroll
        for (int k16i = 0; k16i < 4; k16i++) {
            int c = (2 * k16i + (g & 1)) ^ (n & 7);
            lmb[p][k16i] = sb + (uint32_t)(n * 128 + c * 16);
        }
    }

    float acc[2][4][4];          // fp32 master accumulators
    uint32_t facc[2][4][2];      // fp16 window accumulators (packed half2 x2)
#pragma unroll
    for (int ma = 0; ma < 2; ma++)
#pragma unroll
        for (int na = 0; na < 4; na++) {
#pragma unroll
            for (int e = 0; e < 4; e++) acc[ma][na][e] = 0.f;
            facc[ma][na][0] = 0u; facc[ma][na][1] = 0u;
        }

    // ---- prologue: B steps 0 and 1 (two cp.async groups), A step 0 (direct STS) ----
#pragma unroll
    for (int i = 0; i < 2; i++) CP_ASYNC16(bdst[i], bsrc[i]);
    CP_COMMIT();
#pragma unroll
    for (int i = 0; i < 2; i++) CP_ASYNC16(bdst[i] + TILE_BYTES, bsrc[i] + KT);
    CP_COMMIT();
    {
        float4 rv[4];
#pragma unroll
        for (int i = 0; i < 4; i++) rv[i] = *(const float4*)(aptr + 4 * i);
        __half2 h;
        uint4 s0, s1;
        h = __floats2half2_rn(rv[0].x, rv[0].y); s0.x = *(uint32_t*)&h;
        h = __floats2half2_rn(rv[0].z, rv[0].w); s0.y = *(uint32_t*)&h;
        h = __floats2half2_rn(rv[1].x, rv[1].y); s0.z = *(uint32_t*)&h;
        h = __floats2half2_rn(rv[1].z, rv[1].w); s0.w = *(uint32_t*)&h;
        h = __floats2half2_rn(rv[2].x, rv[2].y); s1.x = *(uint32_t*)&h;
        h = __floats2half2_rn(rv[2].z, rv[2].w); s1.y = *(uint32_t*)&h;
        h = __floats2half2_rn(rv[3].x, rv[3].y); s1.z = *(uint32_t*)&h;
        h = __floats2half2_rn(rv[3].z, rv[3].w); s1.w = *(uint32_t*)&h;
        *(uint4*)(smem + ast0) = s0;
        *(uint4*)(smem + ast1) = s1;
    }

    int b3 = 0;                    // s % 3
#pragma unroll 1
    for (int s = 0; s < NSTEPS; s++) {
        CP_WAIT1();
        __syncthreads();

        // issue B for step s+2 into slot (s+2)%3 -- safe: everyone is past step s-1
        if (s + 2 < NSTEPS) {
            int b3n = b3 + 2; if (b3n >= 3) b3n -= 3;
            const int koff = (s + 2) * KT;
#pragma unroll
            for (int i = 0; i < 2; i++)
                CP_ASYNC16(bdst[i] + b3n * TILE_BYTES, bsrc[i] + koff);
        }
        CP_COMMIT();

        // prefetch A for step s+1 into registers
        float4 rv[4];
        const bool pf = (s + 1 < NSTEPS);
        if (pf) {
            const int aoff = ((s + 1) >> 1) * TOK_F + ((s + 1) & 1) * KT;
#pragma unroll
            for (int i = 0; i < 4; i++) rv[i] = *(const float4*)(aptr + aoff + 4 * i);
        }

        // compute from A slot (s&1), B slot (s%3) -- fp16 accumulate
        const uint32_t abuf = (uint32_t)((s & 1) * TILE_BYTES);
        const uint32_t bbuf = (uint32_t)(b3 * TILE_BYTES);
#pragma unroll
        for (int k16i = 0; k16i < 4; k16i++) {
            uint32_t a0[4], a1[4], b0[4], b1[4];
            LDMATRIX_X4(a0[0], a0[1], a0[2], a0[3], lma[0][k16i] + abuf);
            LDMATRIX_X4(a1[0], a1[1], a1[2], a1[3], lma[1][k16i] + abuf);
            LDMATRIX_X4(b0[0], b0[1], b0[2], b0[3], lmb[0][k16i] + bbuf);
            LDMATRIX_X4(b1[0], b1[1], b1[2], b1[3], lmb[1][k16i] + bbuf);
            MMAF16(facc[0][0], a0[0], a0[1], a0[2], a0[3], b0[0], b0[1]);
            MMAF16(facc[0][1], a0[0], a0[1], a0[2], a0[3], b0[2], b0[3]);
            MMAF16(facc[0][2], a0[0], a0[1], a0[2], a0[3], b1[0], b1[1]);
            MMAF16(facc[0][3], a0[0], a0[1], a0[2], a0[3], b1[2], b1[3]);
            MMAF16(facc[1][0], a1[0], a1[1], a1[2], a1[3], b0[0], b0[1]);
            MMAF16(facc[1][1], a1[0], a1[1], a1[2], a1[3], b0[2], b0[3]);
            MMAF16(facc[1][2], a1[0], a1[1], a1[2], a1[3], b1[0], b1[1]);
            MMAF16(facc[1][3], a1[0], a1[1], a1[2], a1[3], b1[2], b1[3]);
        }

        // flush fp16 window into fp32 every 2 steps (s odd; NSTEPS even -> last covered)
        if (s & 1) {
#pragma unroll
            for (int ma = 0; ma < 2; ma++)
#pragma unroll
                for (int na = 0; na < 4; na++) {
                    float2 f0 = __half22float2(*reinterpret_cast<__half2*>(&facc[ma][na][0]));
                    float2 f1 = __half22float2(*reinterpret_cast<__half2*>(&facc[ma][na][1]));
                    acc[ma][na][0] += f0.x; acc[ma][na][1] += f0.y;
                    acc[ma][na][2] += f1.x; acc[ma][na][3] += f1.y;
                    facc[ma][na][0] = 0u; facc[ma][na][1] = 0u;
                }
        }

        // store prefetched A into slot (s+1)&1 -- safe after syncthreads(s)
        if (pf) {
            const uint32_t nbuf = (uint32_t)(((s + 1) & 1) * TILE_BYTES);
            __half2 h;
            uint4 s0, s1;
            h = __floats2half2_rn(rv[0].x, rv[0].y); s0.x = *(uint32_t*)&h;
            h = __floats2half2_rn(rv[0].z, rv[0].w); s0.y = *(uint32_t*)&h;
            h = __floats2half2_rn(rv[1].x, rv[1].y); s0.z = *(uint32_t*)&h;
            h = __floats2half2_rn(rv[1].z, rv[1].w); s0.w = *(uint32_t*)&h;
            h = __floats2half2_rn(rv[2].x, rv[2].y); s1.x = *(uint32_t*)&h;
            h = __floats2half2_rn(rv[2].z, rv[2].w); s1.y = *(uint32_t*)&h;
            h = __floats2half2_rn(rv[3].x, rv[3].y); s1.z = *(uint32_t*)&h;
            h = __floats2half2_rn(rv[3].z, rv[3].w); s1.w = *(uint32_t*)&h;
            *(uint4*)(smem + ast0 + nbuf) = s0;
            *(uint4*)(smem + ast1 + nbuf) = s1;
        }

        b3 += 1; if (b3 >= 3) b3 -= 3;
    }

    // ---- epilogue ----
    const int Rmax = total_out * 4;
    const int l4 = lid >> 2, lc = lid & 3;
#pragma unroll
    for (int ma = 0; ma < 2; ma++) {
        int R0 = o0 * 4 + wr * 32 + ma * 16 + l4;
#pragma unroll
        for (int na = 0; na < 4; na++) {
            int col = wc * 32 + na * 8 + lc * 2;
            if (R0 < Rmax)
                *(float2*)(outp + (size_t)R0 * 128 + col) =
                    make_float2(acc[ma][na][0], acc[ma][na][1]);
            if (R0 + 8 < Rmax)
                *(float2*)(outp + (size_t)(R0 + 8) * 128 + col) =
                    make_float2(acc[ma][na][2], acc[ma][na][3]);
        }
    }
}

// ---------------- launch ----------------
extern "C" void kernel_launch(void* const* d_in, const int* in_sizes, int n_in,
                              void* d_out, int out_size) {
    const float* k  = (const float*)d_in[0];
    const float* v  = (const float*)d_in[1];
    const float* wk = (const float*)d_in[2];
    const float* wv = (const float*)d_in[3];
    const int*   cu = (const int*)d_in[4];
    int nseq = in_sizes[4] - 1;
    int total_tokens = in_sizes[0] / (N_HEADS * H_DIM);

    prep_kernel<<<1025, dim3(32, 8)>>>(cu, nseq, wk, wv, (float*)d_out);

    int max_out = total_tokens / STRIDE;
    int ntiles = (max_out + 31) / 32;
    cudaFuncSetAttribute(gemm_kernel, cudaFuncAttributeMaxDynamicSharedMemorySize, SMEM_GEMM);
    gemm_kernel<<<dim3(ntiles, 2), 512, SMEM_GEMM>>>(k, v, (float*)d_out);
}

// round 6
// speedup vs baseline: 1.4180x; 1.0020x over previous
#include <cuda_runtime.h>
#include <cuda_fp16.h>
#include <cstdint>

#define N_HEADS 4
#define H_DIM   128
#define TOK_F   512
#define K_DIM   4096
#define BLK     32
#define STRIDE  16
#define MAXSEQ  256

#define NSTEPS  64
#define KT      64              // K halves per step
#define A_BYTES 8192            // 64 rows x 128B
#define B_BYTES 16384           // 128 rows x 128B
#define SMEM_GEMM (2 * A_BYTES + 3 * B_BYTES + 128)

// ---------------- device scratch ----------------
__device__ int    g_bases[65536];
__device__ int    g_total_out;
__device__ __half g_wT[2][(size_t)K_DIM * H_DIM];   // [mat][n*4096 + k] = w[k*128+n]

static __device__ __forceinline__ uint32_t smem_u32(const void* p) {
    uint32_t a;
    asm("{ .reg .u64 t; cvta.to.shared.u64 t, %1; cvt.u32.u64 %0, t; }" : "=r"(a) : "l"(p));
    return a;
}

#define CP_ASYNC16(dst, src) \
    asm volatile("cp.async.cg.shared.global [%0], [%1], 16;" :: "r"(dst), "l"(src) : "memory")
#define CP_COMMIT() asm volatile("cp.async.commit_group;" ::: "memory")
#define CP_WAIT1()  asm volatile("cp.async.wait_group 1;" ::: "memory")

#define LDMATRIX_X4(r0, r1, r2, r3, addr) \
    asm volatile("ldmatrix.sync.aligned.m8n8.x4.shared.b16 {%0,%1,%2,%3}, [%4];" \
                 : "=r"(r0), "=r"(r1), "=r"(r2), "=r"(r3) : "r"(addr))

// fp16-accumulate MMA: D,C packed half2 x2
#define MMAF16(c, a0, a1, a2, a3, b0, b1) \
    asm volatile("mma.sync.aligned.m16n8k16.row.col.f16.f16.f16.f16 " \
                 "{%0,%1}, {%2,%3,%4,%5}, {%6,%7}, {%0,%1};" \
                 : "+r"((c)[0]), "+r"((c)[1]) \
                 : "r"(a0), "r"(a1), "r"(a2), "r"(a3), "r"(b0), "r"(b1))

// ---------------- kernel 1: prep = ragged metadata + W transpose/convert ----------------
__global__ void prep_kernel(const int* __restrict__ cu, int nseq,
                            const float* __restrict__ wk, const float* __restrict__ wv,
                            float* __restrict__ dout) {
    if (blockIdx.x == 1024) {
        __shared__ int s_ol[MAXSEQ];
        __shared__ int s_cu[MAXSEQ + 1];
        int t = threadIdx.y * 32 + threadIdx.x;
        if (t < nseq) {
            int n = cu[t + 1] - cu[t];
            s_ol[t] = (n >= BLK) ? (n - BLK) / STRIDE : 0;
        }
        __syncthreads();
        if (t == 0) {
            int acc = 0;
            s_cu[0] = 0;
            for (int b = 0; b < nseq; b++) { acc += s_ol[b]; s_cu[b + 1] = acc; }
            g_total_out = acc;
        }
        __syncthreads();
        int total = s_cu[nseq];
        for (int i = t; i <= nseq; i += 256)
            dout[(size_t)2 * total * 512 + i] = (float)s_cu[i];
        for (int o = t; o < total; o += 256) {
            int b = 0;
            while (s_cu[b + 1] <= o) b++;
            g_bases[o] = cu[b] + (o - s_cu[b]) * STRIDE;
        }
        return;
    }
    __shared__ float tile[32][33];
    int bx = blockIdx.x;
    int z   = bx >> 9;
    int rem = bx & 511;
    int kb  = rem & 127;
    int nb  = rem >> 7;
    const float* w = z ? wv : wk;
    __half* out = g_wT[z];
    int k0 = kb * 32, n0 = nb * 32;
    int tx = threadIdx.x, ty = threadIdx.y;   // (32, 8)
#pragma unroll
    for (int i = 0; i < 32; i += 8)
        tile[ty + i][tx] = w[(size_t)(k0 + ty + i) * H_DIM + n0 + tx];
    __syncthreads();
#pragma unroll
    for (int i = 0; i < 32; i += 8)
        out[(size_t)(n0 + ty + i) * K_DIM + k0 + tx] = __float2half_rn(tile[tx][ty + i]);
}

// ---------------- kernel 2: HMMA GEMM ----------------
// 256 thr = 8 warps in 2(M) x 4(N); warp tile 32x32; CTA tile 64x128; K-step 64.
// 2 CTAs/SM for cross-CTA latency hiding. fp16 acc over 2-step window, fp32 flush.
__global__ __launch_bounds__(256, 2)
void gemm_kernel(const float* __restrict__ kin, const float* __restrict__ vin,
                 float* __restrict__ dout) {
    extern __shared__ __align__(128) char smem[];
    const uint32_t sa = smem_u32(smem);            // A: 2 x 8KB
    const uint32_t sb = sa + 2 * A_BYTES;          // B: 3 x 16KB
    int* s_base = (int*)(smem + 2 * A_BYTES + 3 * B_BYTES);

    const int tid = threadIdx.x;
    const int wid = tid >> 5;
    const int lid = tid & 31;
    const int total_out = g_total_out;
    const int o0 = blockIdx.x * 16;               // 16 output blocks (64 rows) per CTA
    if (o0 >= total_out) return;

    const int mat = blockIdx.y;
    const float* __restrict__ x = mat ? vin : kin;
    const __half* __restrict__ wT = g_wT[mat];
    float* __restrict__ outp = dout + (size_t)mat * (size_t)total_out * 512;

    if (tid < 16) {
        int o = o0 + tid;
        if (o >= total_out) o = total_out - 1;
        s_base[tid] = g_bases[o];
    }
    __syncthreads();

    // ---- A: thread handles row m = tid>>2 (0..63), float cols q*16..+15 ----
    const int m_row = tid >> 2;
    const int q     = tid & 3;
    const float* aptr = x + (size_t)s_base[m_row >> 2] * TOK_F
                          + (size_t)(m_row & 3) * H_DIM + q * 16;
    const uint32_t ast0 = (uint32_t)(m_row * 128 + (((2 * q)     ^ (m_row & 7)) * 16));
    const uint32_t ast1 = (uint32_t)(m_row * 128 + (((2 * q + 1) ^ (m_row & 7)) * 16));

    // ---- B cp.async: thread handles n = tid>>1 (0..127), chunks (tid&1)*4 + i ----
    const __half* bsrc0;
    uint32_t bdst[4];
    {
        int n = tid >> 1, c0 = (tid & 1) * 4;
        bsrc0 = wT + (size_t)n * K_DIM + c0 * 8;
#pragma unroll
        for (int i = 0; i < 4; i++)
            bdst[i] = sb + (uint32_t)(n * 128 + (((c0 + i) ^ (n & 7)) * 16));
    }

    // ---- ldmatrix addresses ----
    const int wr = wid >> 2;       // M position 0..1
    const int wc = wid & 3;        // N position 0..3
    const int g  = lid >> 3;       // tile group 0..3
    const int l7 = lid & 7;
    uint32_t lma[2][4];
#pragma unroll
    for (int ma = 0; ma < 2; ma++) {
        int r = wr * 32 + ma * 16 + (g & 1) * 8 + l7;
#pragma unroll
        for (int k16i = 0; k16i < 4; k16i++) {
            int c = (2 * k16i + (g >> 1)) ^ (r & 7);
            lma[ma][k16i] = sa + (uint32_t)(r * 128 + c * 16);
        }
    }
    uint32_t lmb[2][4];
#pragma unroll
    for (int p = 0; p < 2; p++) {
        int n = wc * 32 + (2 * p + (g >> 1)) * 8 + l7;
#pragma unroll
        for (int k16i = 0; k16i < 4; k16i++) {
            int c = (2 * k16i + (g & 1)) ^ (n & 7);
            lmb[p][k16i] = sb + (uint32_t)(n * 128 + c * 16);
        }
    }

    float acc[2][4][4];          // fp32 master accumulators
    uint32_t facc[2][4][2];      // fp16 window accumulators
#pragma unroll
    for (int ma = 0; ma < 2; ma++)
#pragma unroll
        for (int na = 0; na < 4; na++) {
#pragma unroll
            for (int e = 0; e < 4; e++) acc[ma][na][e] = 0.f;
            facc[ma][na][0] = 0u; facc[ma][na][1] = 0u;
        }

    // ---- prologue: B steps 0,1; A step 0 ----
#pragma unroll
    for (int i = 0; i < 4; i++) CP_ASYNC16(bdst[i], bsrc0 + i * 8);
    CP_COMMIT();
#pragma unroll
    for (int i = 0; i < 4; i++) CP_ASYNC16(bdst[i] + B_BYTES, bsrc0 + KT + i * 8);
    CP_COMMIT();
    {
        float4 rv[4];
#pragma unroll
        for (int i = 0; i < 4; i++) rv[i] = *(const float4*)(aptr + 4 * i);
        __half2 h;
        uint4 s0, s1;
        h = __floats2half2_rn(rv[0].x, rv[0].y); s0.x = *(uint32_t*)&h;
        h = __floats2half2_rn(rv[0].z, rv[0].w); s0.y = *(uint32_t*)&h;
        h = __floats2half2_rn(rv[1].x, rv[1].y); s0.z = *(uint32_t*)&h;
        h = __floats2half2_rn(rv[1].z, rv[1].w); s0.w = *(uint32_t*)&h;
        h = __floats2half2_rn(rv[2].x, rv[2].y); s1.x = *(uint32_t*)&h;
        h = __floats2half2_rn(rv[2].z, rv[2].w); s1.y = *(uint32_t*)&h;
        h = __floats2half2_rn(rv[3].x, rv[3].y); s1.z = *(uint32_t*)&h;
        h = __floats2half2_rn(rv[3].z, rv[3].w); s1.w = *(uint32_t*)&h;
        *(uint4*)(smem + ast0) = s0;
        *(uint4*)(smem + ast1) = s1;
    }

    int b3 = 0;                    // s % 3
#pragma unroll 1
    for (int s = 0; s < NSTEPS; s++) {
        CP_WAIT1();
        __syncthreads();

        // issue B for step s+2 into slot (s+2)%3 -- safe: everyone is past step s-1
        if (s + 2 < NSTEPS) {
            int b3n = b3 + 2; if (b3n >= 3) b3n -= 3;
            const int koff = (s + 2) * KT;
#pragma unroll
            for (int i = 0; i < 4; i++)
                CP_ASYNC16(bdst[i] + b3n * B_BYTES, bsrc0 + koff + i * 8);
        }
        CP_COMMIT();

        // prefetch A for step s+1
        float4 rv[4];
        const bool pf = (s + 1 < NSTEPS);
        if (pf) {
            const int aoff = ((s + 1) >> 1) * TOK_F + ((s + 1) & 1) * KT;
#pragma unroll
            for (int i = 0; i < 4; i++) rv[i] = *(const float4*)(aptr + aoff + 4 * i);
        }

        // compute from A slot (s&1), B slot (s%3)
        const uint32_t abuf = (uint32_t)((s & 1) * A_BYTES);
        const uint32_t bbuf = (uint32_t)(b3 * B_BYTES);
#pragma unroll
        for (int k16i = 0; k16i < 4; k16i++) {
            uint32_t a0[4], a1[4], b0[4], b1[4];
            LDMATRIX_X4(a0[0], a0[1], a0[2], a0[3], lma[0][k16i] + abuf);
            LDMATRIX_X4(a1[0], a1[1], a1[2], a1[3], lma[1][k16i] + abuf);
            LDMATRIX_X4(b0[0], b0[1], b0[2], b0[3], lmb[0][k16i] + bbuf);
            LDMATRIX_X4(b1[0], b1[1], b1[2], b1[3], lmb[1][k16i] + bbuf);
            MMAF16(facc[0][0], a0[0], a0[1], a0[2], a0[3], b0[0], b0[1]);
            MMAF16(facc[0][1], a0[0], a0[1], a0[2], a0[3], b0[2], b0[3]);
            MMAF16(facc[0][2], a0[0], a0[1], a0[2], a0[3], b1[0], b1[1]);
            MMAF16(facc[0][3], a0[0], a0[1], a0[2], a0[3], b1[2], b1[3]);
            MMAF16(facc[1][0], a1[0], a1[1], a1[2], a1[3], b0[0], b0[1]);
            MMAF16(facc[1][1], a1[0], a1[1], a1[2], a1[3], b0[2], b0[3]);
            MMAF16(facc[1][2], a1[0], a1[1], a1[2], a1[3], b1[0], b1[1]);
            MMAF16(facc[1][3], a1[0], a1[1], a1[2], a1[3], b1[2], b1[3]);
        }

        // flush fp16 window into fp32 every 2 steps
        if (s & 1) {
#pragma unroll
            for (int ma = 0; ma < 2; ma++)
#pragma unroll
                for (int na = 0; na < 4; na++) {
                    float2 f0 = __half22float2(*reinterpret_cast<__half2*>(&facc[ma][na][0]));
                    float2 f1 = __half22float2(*reinterpret_cast<__half2*>(&facc[ma][na][1]));
                    acc[ma][na][0] += f0.x; acc[ma][na][1] += f0.y;
                    acc[ma][na][2] += f1.x; acc[ma][na][3] += f1.y;
                    facc[ma][na][0] = 0u; facc[ma][na][1] = 0u;
                }
        }

        // store prefetched A into slot (s+1)&1 -- safe after syncthreads(s)
        if (pf) {
            const uint32_t nbuf = (uint32_t)(((s + 1) & 1) * A_BYTES);
            __half2 h;
            uint4 s0, s1;
            h = __floats2half2_rn(rv[0].x, rv[0].y); s0.x = *(uint32_t*)&h;
            h = __floats2half2_rn(rv[0].z, rv[0].w); s0.y = *(uint32_t*)&h;
            h = __floats2half2_rn(rv[1].x, rv[1].y); s0.z = *(uint32_t*)&h;
            h = __floats2half2_rn(rv[1].z, rv[1].w); s0.w = *(uint32_t*)&h;
            h = __floats2half2_rn(rv[2].x, rv[2].y); s1.x = *(uint32_t*)&h;
            h = __floats2half2_rn(rv[2].z, rv[2].w); s1.y = *(uint32_t*)&h;
            h = __floats2half2_rn(rv[3].x, rv[3].y); s1.z = *(uint32_t*)&h;
            h = __floats2half2_rn(rv[3].z, rv[3].w); s1.w = *(uint32_t*)&h;
            *(uint4*)(smem + ast0 + nbuf) = s0;
            *(uint4*)(smem + ast1 + nbuf) = s1;
        }

        b3 += 1; if (b3 >= 3) b3 -= 3;
    }

    // ---- epilogue ----
    const int Rmax = total_out * 4;
    const int l4 = lid >> 2, lc = lid & 3;
#pragma unroll
    for (int ma = 0; ma < 2; ma++) {
        int R0 = o0 * 4 + wr * 32 + ma * 16 + l4;
#pragma unroll
        for (int na = 0; na < 4; na++) {
            int col = wc * 32 + na * 8 + lc * 2;
            if (R0 < Rmax)
                *(float2*)(outp + (size_t)R0 * 128 + col) =
                    make_float2(acc[ma][na][0], acc[ma][na][1]);
            if (R0 + 8 < Rmax)
                *(float2*)(outp + (size_t)(R0 + 8) * 128 + col) =
                    make_float2(acc[ma][na][2], acc[ma][na][3]);
        }
    }
}

// ---------------- launch ----------------
extern "C" void kernel_launch(void* const* d_in, const int* in_sizes, int n_in,
                              void* d_out, int out_size) {
    const float* k  = (const float*)d_in[0];
    const float* v  = (const float*)d_in[1];
    const float* wk = (const float*)d_in[2];
    const float* wv = (const float*)d_in[3];
    const int*   cu = (const int*)d_in[4];
    int nseq = in_sizes[4] - 1;
    int total_tokens = in_sizes[0] / (N_HEADS * H_DIM);

    prep_kernel<<<1025, dim3(32, 8)>>>(cu, nseq, wk, wv, (float*)d_out);

    int max_out = total_tokens / STRIDE;
    int ntiles = (max_out + 15) / 16;
    cudaFuncSetAttribute(gemm_kernel, cudaFuncAttributeMaxDynamicSharedMemorySize, SMEM_GEMM);
    gemm_kernel<<<dim3(ntiles, 2), 256, SMEM_GEMM>>>(k, v, (float*)d_out);
}